// round 8
// baseline (speedup 1.0000x reference)
#include <cuda_runtime.h>

#define Nn 50000
#define Rr 16
#define Hh 32
#define Ll 8
#define Ee 1600000

// Scratch (static __device__ arrays: allocation-free per harness rules)
__device__ __align__(16) int   g_cnt[Rr * Nn];       // per-(relation,dst) edge counts
__device__ __align__(16) float g_enorm[Ee];          // per-edge 1/deg_r(dst)
__device__ __align__(16) float g_h1[Nn * Hh];        // layer-1 hidden (agg -> relu'd)
__device__ __align__(16) float g_T[Rr * Nn * Ll];    // T[r,n,l] = (h1[n,:] @ W2[r])[l]

// Vector reduction: 4x fp32 add in one L2 atomic op (sm_90+)
__device__ __forceinline__ void red_add_v4(float* p, float4 v) {
    asm volatile("red.global.add.v4.f32 [%0], {%1,%2,%3,%4};"
                 :: "l"(p), "f"(v.x), "f"(v.y), "f"(v.z), "f"(v.w)
                 : "memory");
}

// Packed f32x2 FMA (sm_103a): acc = a * b + acc, two fp32 lanes per op
__device__ __forceinline__ void fma_f32x2(unsigned long long& acc,
                                          unsigned long long a,
                                          unsigned long long b) {
    asm("fma.rn.f32x2 %0, %1, %2, %0;" : "+l"(acc) : "l"(a), "l"(b));
}
__device__ __forceinline__ unsigned long long pack_f32x2(float lo, float hi) {
    unsigned long long r;
    asm("mov.b64 %0, {%1, %2};" : "=l"(r) : "f"(lo), "f"(hi));
    return r;
}
__device__ __forceinline__ void unpack_f32x2(unsigned long long v, float& lo, float& hi) {
    asm("mov.b64 {%0, %1}, %2;" : "=f"(lo), "=f"(hi) : "l"(v));
}

// ---------------------------------------------------------------------------
// Zero accumulators (g_cnt, g_h1). out is initialized by k_T now.
// ---------------------------------------------------------------------------
__global__ void k_zero() {
    int i = blockIdx.x * blockDim.x + threadIdx.x;
    int stride = gridDim.x * blockDim.x;
    float4 z = make_float4(0.f, 0.f, 0.f, 0.f);
    int4* c4 = (int4*)g_cnt;
    float4* h4 = (float4*)g_h1;
    for (int j = i; j < (Rr * Nn) / 4; j += stride) c4[j] = make_int4(0, 0, 0, 0);
    for (int j = i; j < (Nn * Hh) / 4; j += stride) h4[j] = z;
}

// ---------------------------------------------------------------------------
// Per-(relation,dst) edge counts. 8 edges per thread (MLP=8).
// ---------------------------------------------------------------------------
__global__ void k_count(const int* __restrict__ et, const int* __restrict__ dst) {
    int t = blockIdx.x * blockDim.x + threadIdx.x;
    if (t >= Ee / 8) return;
    int e0 = t * 8;
    int4 da = *(const int4*)(dst + e0);
    int4 db = *(const int4*)(dst + e0 + 4);
    int4 ra = *(const int4*)(et + e0);
    int4 rb = *(const int4*)(et + e0 + 4);
    atomicAdd(&g_cnt[ra.x * Nn + da.x], 1);
    atomicAdd(&g_cnt[ra.y * Nn + da.y], 1);
    atomicAdd(&g_cnt[ra.z * Nn + da.z], 1);
    atomicAdd(&g_cnt[ra.w * Nn + da.w], 1);
    atomicAdd(&g_cnt[rb.x * Nn + db.x], 1);
    atomicAdd(&g_cnt[rb.y * Nn + db.y], 1);
    atomicAdd(&g_cnt[rb.z * Nn + db.z], 1);
    atomicAdd(&g_cnt[rb.w * Nn + db.w], 1);
}

// ---------------------------------------------------------------------------
// Per-edge norm: enorm[e] = 1/max(cnt[r*N+d],1). Scattered cnt gather lives
// HERE (a cheap standalone pass) instead of inside the L1-saturated layer1.
// ---------------------------------------------------------------------------
__global__ void k_enorm(const int* __restrict__ et, const int* __restrict__ dst) {
    int t = blockIdx.x * blockDim.x + threadIdx.x;
    if (t >= Ee / 8) return;
    int e0 = t * 8;
    int4 da = *(const int4*)(dst + e0);
    int4 db = *(const int4*)(dst + e0 + 4);
    int4 ra = *(const int4*)(et + e0);
    int4 rb = *(const int4*)(et + e0 + 4);
    int dd[8] = {da.x, da.y, da.z, da.w, db.x, db.y, db.z, db.w};
    int rr[8] = {ra.x, ra.y, ra.z, ra.w, rb.x, rb.y, rb.z, rb.w};
    int c[8];
#pragma unroll
    for (int k = 0; k < 8; k++) c[k] = g_cnt[rr[k] * Nn + dd[k]];
    float n[8];
#pragma unroll
    for (int k = 0; k < 8; k++) n[k] = 1.0f / fmaxf((float)c[k], 1.0f);
    *(float4*)(g_enorm + e0)     = make_float4(n[0], n[1], n[2], n[3]);
    *(float4*)(g_enorm + e0 + 4) = make_float4(n[4], n[5], n[6], n[7]);
}

// ---------------------------------------------------------------------------
// Layer 1: 8 threads per edge (quarter-row each), 4 edges per thread.
//   g_h1[dst, q*4..q*4+3] += W1[r, src, q*4..] * enorm[e]
// enorm is now a single broadcast float4 load per edge-quad (no gather).
// ---------------------------------------------------------------------------
__global__ void k_layer1(const int* __restrict__ src, const int* __restrict__ dst,
                         const int* __restrict__ et, const float* __restrict__ W1) {
    int g = blockIdx.x * blockDim.x + threadIdx.x;
    int grp = g >> 3;        // which edge-quad
    int q = g & 7;           // which quarter of the 32-wide row
    if (grp >= Ee / 4) return;
    int e0 = grp * 4;

    int4 s4 = *(const int4*)(src + e0);
    int4 d4 = *(const int4*)(dst + e0);
    int4 r4 = *(const int4*)(et + e0);
    float4 n4 = *(const float4*)(g_enorm + e0);
    int ss[4] = {s4.x, s4.y, s4.z, s4.w};
    int dd[4] = {d4.x, d4.y, d4.z, d4.w};
    int rr[4] = {r4.x, r4.y, r4.z, r4.w};
    float nn[4] = {n4.x, n4.y, n4.z, n4.w};

    float4 ww[4];
#pragma unroll
    for (int k = 0; k < 4; k++) {
        ww[k] = *(const float4*)(W1 + (rr[k] * Nn + ss[k]) * Hh + q * 4);
    }
#pragma unroll
    for (int k = 0; k < 4; k++) {
        float4 v = make_float4(ww[k].x * nn[k], ww[k].y * nn[k],
                               ww[k].z * nn[k], ww[k].w * nn[k]);
        red_add_v4(&g_h1[dd[k] * Hh + q * 4], v);
    }
}

// ---------------------------------------------------------------------------
// Fused:  h1 = relu(agg1 + root1 + b1)          (stored back to g_h1)
//         out_base[n,l] = (h1 @ root2)[l] + b2  (layer2 REDs onto this)
//         T[r,n,l] = sum_h h1[n,h] * W2[r,h,l]
// Block = 64 nodes x 4 l-pair threads. f32x2 packed FMAs.
// ---------------------------------------------------------------------------
__global__ void k_T(const float* __restrict__ W2, const float* __restrict__ root1,
                    const float* __restrict__ b1, const float* __restrict__ root2,
                    const float* __restrict__ b2, float* __restrict__ out) {
    __shared__ float sW[Rr * Hh * Ll];   // [r][h][l], 16KB
    __shared__ float sR[Hh * Ll];        // root2 [h][l], 1KB
    __shared__ float sB1[Hh];
    __shared__ float sB2[Ll];
    for (int i = threadIdx.x; i < Rr * Hh * Ll; i += blockDim.x) sW[i] = W2[i];
    for (int i = threadIdx.x; i < Hh * Ll; i += blockDim.x) sR[i] = root2[i];
    if (threadIdx.x < Hh) sB1[threadIdx.x] = b1[threadIdx.x];
    if (threadIdx.x < Ll) sB2[threadIdx.x] = b2[threadIdx.x];
    __syncthreads();

    int n = blockIdx.x * 64 + (threadIdx.x >> 2);
    int lp = threadIdx.x & 3;            // l-pair index: l = 2*lp, 2*lp+1
    if (n >= Nn) return;

    // Load raw agg + root1, apply relu -> h[32]
    float h[Hh];
    const float4* ap = (const float4*)(g_h1 + n * Hh);
    const float4* rp = (const float4*)(root1 + n * Hh);
#pragma unroll
    for (int j = 0; j < 8; j++) {
        float4 av = ap[j];
        float4 rv = rp[j];
        h[j * 4 + 0] = fmaxf(av.x + rv.x + sB1[j * 4 + 0], 0.0f);
        h[j * 4 + 1] = fmaxf(av.y + rv.y + sB1[j * 4 + 1], 0.0f);
        h[j * 4 + 2] = fmaxf(av.z + rv.z + sB1[j * 4 + 2], 0.0f);
        h[j * 4 + 3] = fmaxf(av.w + rv.w + sB1[j * 4 + 3], 0.0f);
    }
    // One thread per node writes back relu'd h1 (k_final no longer needs it,
    // but keep g_h1 consistent; also cheap)
    if (lp == 0) {
        float4* hw = (float4*)(g_h1 + n * Hh);
#pragma unroll
        for (int j = 0; j < 8; j++)
            hw[j] = make_float4(h[j * 4], h[j * 4 + 1], h[j * 4 + 2], h[j * 4 + 3]);
    }

    // out base: y(l=2lp, 2lp+1) = h @ root2 + b2
    {
        unsigned long long yacc = pack_f32x2(sB2[lp * 2], sB2[lp * 2 + 1]);
#pragma unroll
        for (int hh = 0; hh < Hh; hh++) {
            const float2* rp2 = (const float2*)(sR + hh * Ll + lp * 2);
            float2 rv = *rp2;
            fma_f32x2(yacc, pack_f32x2(h[hh], h[hh]), pack_f32x2(rv.x, rv.y));
        }
        float lo, hi;
        unpack_f32x2(yacc, lo, hi);
        *(float2*)(out + n * Ll + lp * 2) = make_float2(lo, hi);
    }

    unsigned long long acc[Rr];
#pragma unroll
    for (int r = 0; r < Rr; r++) acc[r] = pack_f32x2(0.0f, 0.0f);

#pragma unroll
    for (int hh = 0; hh < Hh; hh++) {
        unsigned long long hv = pack_f32x2(h[hh], h[hh]);
#pragma unroll
        for (int r = 0; r < Rr; r++) {
            const float2* wp = (const float2*)(sW + (r * Hh + hh) * Ll + lp * 2);
            float2 w = *wp;
            fma_f32x2(acc[r], hv, pack_f32x2(w.x, w.y));
        }
    }
#pragma unroll
    for (int r = 0; r < Rr; r++) {
        float lo, hi;
        unpack_f32x2(acc[r], lo, hi);
        float2* tp = (float2*)(g_T + (r * Nn + n) * Ll + lp * 2);
        *tp = make_float2(lo, hi);
    }
}

// ---------------------------------------------------------------------------
// Layer 2 edge pass: 2 threads per edge (half-row each), 8 edges per thread.
//   out[dst, half*4..] += enorm[e] * T[r, src, half*4..]
// ---------------------------------------------------------------------------
__global__ void k_layer2(const int* __restrict__ src, const int* __restrict__ dst,
                         const int* __restrict__ et, float* __restrict__ out) {
    int g = blockIdx.x * blockDim.x + threadIdx.x;
    int oct = g >> 1;
    int half = g & 1;
    if (oct >= Ee / 8) return;
    int e0 = oct * 8;

    int4 sa = *(const int4*)(src + e0);
    int4 sb = *(const int4*)(src + e0 + 4);
    int4 da = *(const int4*)(dst + e0);
    int4 db = *(const int4*)(dst + e0 + 4);
    int4 ra = *(const int4*)(et + e0);
    int4 rb = *(const int4*)(et + e0 + 4);
    float4 na = *(const float4*)(g_enorm + e0);
    float4 nb = *(const float4*)(g_enorm + e0 + 4);
    int ss[8] = {sa.x, sa.y, sa.z, sa.w, sb.x, sb.y, sb.z, sb.w};
    int dd[8] = {da.x, da.y, da.z, da.w, db.x, db.y, db.z, db.w};
    int rr[8] = {ra.x, ra.y, ra.z, ra.w, rb.x, rb.y, rb.z, rb.w};
    float nn[8] = {na.x, na.y, na.z, na.w, nb.x, nb.y, nb.z, nb.w};

    float4 tv[8];
#pragma unroll
    for (int k = 0; k < 8; k++) {
        tv[k] = *(const float4*)(g_T + (rr[k] * Nn + ss[k]) * Ll + half * 4);
    }
#pragma unroll
    for (int k = 0; k < 8; k++) {
        float4 v = make_float4(tv[k].x * nn[k], tv[k].y * nn[k],
                               tv[k].z * nn[k], tv[k].w * nn[k]);
        red_add_v4(&out[dd[k] * Ll + half * 4], v);
    }
}

// ---------------------------------------------------------------------------
// Final: out = sigmoid(out), elementwise (base + edge REDs already in out)
// ---------------------------------------------------------------------------
__global__ void k_final(float* __restrict__ out) {
    int i = blockIdx.x * blockDim.x + threadIdx.x;
    if (i >= (Nn * Ll) / 4) return;
    float4 v = ((const float4*)out)[i];
    v.x = 1.0f / (1.0f + expf(-v.x));
    v.y = 1.0f / (1.0f + expf(-v.y));
    v.z = 1.0f / (1.0f + expf(-v.z));
    v.w = 1.0f / (1.0f + expf(-v.w));
    ((float4*)out)[i] = v;
}

// ---------------------------------------------------------------------------
extern "C" void kernel_launch(void* const* d_in, const int* in_sizes, int n_in,
                              void* d_out, int out_size) {
    const int* ei    = (const int*)d_in[0];    // edge_index [2, E]
    const int* et    = (const int*)d_in[1];    // edge_type  [E]
    const float* W1  = (const float*)d_in[2];  // [R, N, H]
    const float* rt1 = (const float*)d_in[3];  // [N, H]
    const float* b1  = (const float*)d_in[4];  // [H]
    const float* W2  = (const float*)d_in[5];  // [R, H, L]
    const float* rt2 = (const float*)d_in[6];  // [H, L]
    const float* b2  = (const float*)d_in[7];  // [L]
    float* out = (float*)d_out;                // [N, L]

    const int* src = ei;
    const int* dst = ei + Ee;

    k_zero<<<1024, 256>>>();
    k_count<<<(Ee / 8 + 255) / 256, 256>>>(et, dst);
    k_enorm<<<(Ee / 8 + 255) / 256, 256>>>(et, dst);
    k_layer1<<<(Ee / 4) * 8 / 256, 256>>>(src, dst, et, W1);     // 8 thr/edge, 4 edges/thr
    k_T<<<(Nn + 63) / 64, 256>>>(W2, rt1, b1, rt2, b2, out);     // relu + T + out-base
    k_layer2<<<((Ee / 8) * 2 + 255) / 256, 256>>>(src, dst, et, out); // 2 thr/edge, 8 edges/thr
    k_final<<<((Nn * Ll) / 4 + 255) / 256, 256>>>(out);
}